// round 17
// baseline (speedup 1.0000x reference)
#include <cuda_runtime.h>
#include <cuda_fp16.h>
#include <math.h>
#include <stdint.h>

// ---------------- problem constants ----------------
#define BATCH   128
#define CHAN    3
#define HW      224
#define PATCH   16
#define NPD     14
#define NPATCH  (NPD*NPD)           // 196
#define M_DIM   (BATCH*NPATCH)      // 25088
#define K_DIM   (CHAN*PATCH*PATCH)  // 768
#define N_DIM   768
#define IMG_STRIDE (CHAN*HW*HW)     // 150528
#define CH_STRIDE  (HW*HW)          // 50176

#define PI_D 3.141592653589793238462643383279502884

#define NTILE_M 196
#define NTILE_N 6
#define NTILES  (NTILE_M * NTILE_N)   // 1176

// fp16 scratch + coordination state
__device__ __half g_wt[N_DIM * K_DIM];
__device__ __half g_xh[(long)M_DIM * K_DIM];
__device__ int g_warrive;                 // producers done with DCT
__device__ volatile int g_aflag[NTILE_M]; // per-m-block A ready
__device__ int g_tile;                    // GEMM tile queue
__device__ int g_done;                    // completion counter (reset protocol)

__device__ __forceinline__ void mma_f16(float* c, const unsigned* a, const unsigned* b) {
    asm volatile(
        "mma.sync.aligned.m16n8k16.row.col.f32.f16.f16.f32 "
        "{%0,%1,%2,%3}, {%4,%5,%6,%7}, {%8,%9}, {%0,%1,%2,%3};"
        : "+f"(c[0]), "+f"(c[1]), "+f"(c[2]), "+f"(c[3])
        : "r"(a[0]), "r"(a[1]), "r"(a[2]), "r"(a[3]), "r"(b[0]), "r"(b[1]));
}
#define LDSM_X4(r0, r1, r2, r3, addr) \
    asm volatile("ldmatrix.sync.aligned.m8n8.x4.shared.b16 {%0,%1,%2,%3}, [%4];" \
                 : "=r"(r0), "=r"(r1), "=r"(r2), "=r"(r3) : "r"(addr))
#define CP_ASYNC16(saddr, gptr) \
    asm volatile("cp.async.cg.shared.global [%0], [%1], 16;" :: "r"(saddr), "l"(gptr))
#define CP_COMMIT()  asm volatile("cp.async.commit_group;" ::: "memory")
#define CP_WAIT(n)   asm volatile("cp.async.wait_group %0;" :: "n"(n) : "memory")

// GEMM tile geometry (proven R10/R16 configuration)
#define BM 128
#define BN 128
#define BK 32
#define STAGES 4
#define NT (K_DIM / BK)          // 24
#define ROWB 80                  // bytes per smem row (64 data + 16 pad)
#define TILE_B (BM * ROWB)       // 10240
#define STG_B (2 * TILE_B)       // 20480
#define SMEM_BYTES (STAGES * STG_B)   // 81920

__global__ __launch_bounds__(256, 2)
void fused_kernel(const float* __restrict__ x, const float* __restrict__ w,
                  const float* __restrict__ bias, float* __restrict__ out,
                  int nprod) {
    extern __shared__ char smem[];
    const unsigned smem_b = (unsigned)__cvta_generic_to_shared(smem);
    const int tid = threadIdx.x;

    // ===================== producer phase =====================
    if ((int)blockIdx.x < nprod) {
        // ---- DCT weight fold (smem staging in dynamic smem) ----
        float* Ws = (float*)smem;          // 256 floats
        float* Ds = (float*)smem + 256;    // 64 floats
        if (tid < 64) {
            int k = tid >> 3, n = tid & 7;
            double v = sqrt(2.0 / 8.0) * cos(PI_D * (2.0 * n + 1.0) * k / 16.0);
            if (k == 0) v *= (1.0 / sqrt(2.0));
            Ds[k * 8 + n] = (float)v;
        }
        __syncthreads();
        const int i = tid >> 4, j = tid & 15;
        const int bi = i & 8, bj = j & 8, ii = i & 7, jj = j & 7;
        for (int oc = blockIdx.x; oc < N_DIM * CHAN; oc += nprod) {
            Ws[tid] = w[oc * 256 + tid];
            __syncthreads();
            float s = 0.0f;
            #pragma unroll
            for (int u = 0; u < 8; u++) {
                float du = Ds[u * 8 + ii];
                #pragma unroll
                for (int v = 0; v < 8; v++)
                    s += du * Ws[(bi + u) * 16 + bj + v] * Ds[v * 8 + jj];
            }
            int o = oc / CHAN, c = oc % CHAN;
            g_wt[(long)o * K_DIM + c * 256 + i * 16 + j] = __float2half_rn(s);
            __syncthreads();
        }
        __syncthreads();
        __threadfence();
        if (tid == 0) atomicAdd(&g_warrive, 1);

        // ---- im2col m-blocks (flag each when complete) ----
        for (int mb = blockIdx.x; mb < NTILE_M; mb += nprod) {
            for (int u = tid; u < 128 * 48; u += 512) {
                // two units per iteration for MLP (u and u+256)
                #pragma unroll
                for (int h = 0; h < 2; h++) {
                    int uu = u + h * 256;
                    int lm = uu / 48, rem = uu % 48;
                    int c = rem >> 4, ir = rem & 15;
                    int m = mb * 128 + lm;
                    int b = m / NPATCH, pr = m % NPATCH;
                    int ph = pr / NPD, pw = pr % NPD;
                    const float4* src = (const float4*)(x + (long)b * IMG_STRIDE
                        + (long)c * CH_STRIDE + (long)(ph * 16 + ir) * HW + pw * 16);
                    float4 v0 = src[0], v1 = src[1], v2 = src[2], v3 = src[3];
                    __half2 h0 = __floats2half2_rn(v0.x, v0.y);
                    __half2 h1 = __floats2half2_rn(v0.z, v0.w);
                    __half2 h2 = __floats2half2_rn(v1.x, v1.y);
                    __half2 h3 = __floats2half2_rn(v1.z, v1.w);
                    __half2 h4 = __floats2half2_rn(v2.x, v2.y);
                    __half2 h5 = __floats2half2_rn(v2.z, v2.w);
                    __half2 h6 = __floats2half2_rn(v3.x, v3.y);
                    __half2 h7 = __floats2half2_rn(v3.z, v3.w);
                    uint4 o0, o1;
                    o0.x = *(unsigned*)&h0; o0.y = *(unsigned*)&h1;
                    o0.z = *(unsigned*)&h2; o0.w = *(unsigned*)&h3;
                    o1.x = *(unsigned*)&h4; o1.y = *(unsigned*)&h5;
                    o1.z = *(unsigned*)&h6; o1.w = *(unsigned*)&h7;
                    uint4* dst = (uint4*)(g_xh + (long)m * K_DIM + c * 256 + ir * 16);
                    dst[0] = o0; dst[1] = o1;
                }
            }
            __syncthreads();
            __threadfence();
            if (tid == 0) g_aflag[mb] = 1;
            __syncthreads();
        }
    }

    // ===================== consumer phase (all CTAs) =====================
    if (tid == 0) { while (*(volatile int*)&g_warrive < nprod) {} }
    __syncthreads();

    const int lane = tid & 31, wid = tid >> 5;
    const int warp_m = wid >> 1, warp_n = wid & 1;
    const int g = lane >> 2, tig = lane & 3;
    const int row0 = tid >> 2;
    const int q    = tid & 3;
    const unsigned stA0 = row0 * ROWB + q * 16;
    const unsigned stA1 = (row0 + 64) * ROWB + q * 16;

    const int lm_row = lane & 7;
    const int lm_hi  = (lane >> 3) & 1;
    const int lm_k8  = (lane >> 4) * 8;
    unsigned a_off[2];
    #pragma unroll
    for (int mt = 0; mt < 2; mt++)
        a_off[mt] = (warp_m * 32 + mt * 16 + lm_hi * 8 + lm_row) * ROWB + lm_k8 * 2;
    const int b_hi = (lane >> 3) & 1;
    const int b_nt = (lane >> 4);
    unsigned b_off[4];
    #pragma unroll
    for (int g2 = 0; g2 < 4; g2++)
        b_off[g2] = TILE_B + (warp_n * 64 + (2 * g2 + b_nt) * 8 + lm_row) * ROWB
                  + b_hi * 16;

    __shared__ int s_t;
    while (true) {
        if (tid == 0) s_t = atomicAdd(&g_tile, 1);
        __syncthreads();
        const int t = s_t;
        if (t >= NTILES) break;
        const int mb = t / NTILE_N, nb = t % NTILE_N;
        if (tid == 0) { while (g_aflag[mb] == 0) {} }
        __syncthreads();

        const int m0 = mb * BM, n0 = nb * BN;
        const __half* gA0 = g_xh + (long)(m0 + row0) * K_DIM + q * 8;
        const __half* gA1 = g_xh + (long)(m0 + row0 + 64) * K_DIM + q * 8;
        const __half* gB0 = g_wt + (long)(n0 + row0) * K_DIM + q * 8;
        const __half* gB1 = g_wt + (long)(n0 + row0 + 64) * K_DIM + q * 8;

        auto load_tile = [&](int tt, int slot) {
            const unsigned base = smem_b + slot * STG_B;
            const int k0 = tt * BK;
            CP_ASYNC16(base + stA0, gA0 + k0);
            CP_ASYNC16(base + stA1, gA1 + k0);
            CP_ASYNC16(base + TILE_B + stA0, gB0 + k0);
            CP_ASYNC16(base + TILE_B + stA1, gB1 + k0);
        };

        float acc[2][8][4];
        #pragma unroll
        for (int ii2 = 0; ii2 < 2; ii2++)
            #pragma unroll
            for (int jj2 = 0; jj2 < 8; jj2++)
                #pragma unroll
                for (int p = 0; p < 4; p++) acc[ii2][jj2][p] = 0.0f;

        #pragma unroll
        for (int s = 0; s < STAGES - 1; s++) { load_tile(s, s); CP_COMMIT(); }

        auto compute_tile = [&](unsigned base) {
            #pragma unroll
            for (int kk = 0; kk < 2; kk++) {
                unsigned afr[2][4];
                #pragma unroll
                for (int mt = 0; mt < 2; mt++)
                    LDSM_X4(afr[mt][0], afr[mt][1], afr[mt][2], afr[mt][3],
                            base + a_off[mt] + kk * 32);
                unsigned bfr[8][2];
                #pragma unroll
                for (int g2 = 0; g2 < 4; g2++)
                    LDSM_X4(bfr[2 * g2][0], bfr[2 * g2][1],
                            bfr[2 * g2 + 1][0], bfr[2 * g2 + 1][1],
                            base + b_off[g2] + kk * 32);
                #pragma unroll
                for (int mt = 0; mt < 2; mt++)
                    #pragma unroll
                    for (int nt2 = 0; nt2 < 8; nt2++)
                        mma_f16(acc[mt][nt2], afr[mt], bfr[nt2]);
            }
        };

        for (int t0 = 0; t0 < NT; t0 += STAGES) {
            #pragma unroll
            for (int u = 0; u < STAGES; u++) {
                const int tt = t0 + u;
                CP_WAIT(STAGES - 2);
                __syncthreads();
                const int tn = tt + STAGES - 1;
                if (tn < NT) load_tile(tn, tn & (STAGES - 1));
                CP_COMMIT();
                compute_tile(smem_b + u * STG_B);
            }
        }

        // epilogue: bias + store
        #pragma unroll
        for (int mt = 0; mt < 2; mt++) {
            const int r0 = m0 + warp_m * 32 + mt * 16 + g;
            #pragma unroll
            for (int nt2 = 0; nt2 < 8; nt2++) {
                const int col = n0 + warp_n * 64 + nt2 * 8 + 2 * tig;
                const float b0 = bias[col], b1 = bias[col + 1];
                float2 v0 = make_float2(acc[mt][nt2][0] + b0, acc[mt][nt2][1] + b1);
                float2 v1 = make_float2(acc[mt][nt2][2] + b0, acc[mt][nt2][3] + b1);
                *(float2*)(out + (long)r0 * N_DIM + col)       = v0;
                *(float2*)(out + (long)(r0 + 8) * N_DIM + col) = v1;
            }
        }
        // loop-top __syncthreads (after claim) separates this tile's smem reads
        // from the next tile's prologue writes.
    }

    // ---- completion + state reset for next graph replay ----
    __syncthreads();
    if (tid == 0) {
        int d = atomicAdd(&g_done, 1);
        if (d == (int)gridDim.x - 1) {       // last CTA: everyone else finished
            g_done = 0;
            g_tile = 0;
            g_warrive = 0;
            for (int f = 0; f < NTILE_M; f++) g_aflag[f] = 0;
            __threadfence();
        }
    }
}

// ---------------------------------------------------------------------------
extern "C" void kernel_launch(void* const* d_in, const int* in_sizes, int n_in,
                              void* d_out, int out_size) {
    const float* x = (const float*)d_in[0];   // [128,3,224,224]
    const float* w = (const float*)d_in[1];   // [768,3,16,16]
    const float* b = (const float*)d_in[2];   // [768]
    float* out = (float*)d_out;               // [128,196,768]

    int sms = 0;
    cudaDeviceGetAttribute(&sms, cudaDevAttrMultiProcessorCount, 0);
    if (sms <= 0) sms = 148;
    int G = sms * 2;
    int nprod = G / 3;
    if (nprod < 1) nprod = 1;

    cudaFuncSetAttribute(fused_kernel,
                         cudaFuncAttributeMaxDynamicSharedMemorySize, SMEM_BYTES);
    fused_kernel<<<G, 256, SMEM_BYTES>>>(x, w, b, out, nprod);
}